// round 1
// baseline (speedup 1.0000x reference)
#include <cuda_runtime.h>
#include <math.h>

#define TT 5
#define ZZ 32
#define YY 512
#define XX 512
#define N_RAYS 10000
#define N_STEPS 768
#define VOXEL 0.2f

// Scratch: per-ray prediction and gt distance (already scaled by VOXEL).
__device__ float g_pred[N_RAYS];
__device__ float g_gt[N_RAYS];

__global__ void ray_march_kernel(const float* __restrict__ grid,
                                 const float* __restrict__ origin,   // [T,3]
                                 const float* __restrict__ points,   // [N_RAYS,3]
                                 const int*   __restrict__ tindex)   // [N_RAYS]
{
    const unsigned FULL = 0xffffffffu;
    int gwarp = (blockIdx.x * blockDim.x + threadIdx.x) >> 5;
    int lane  = threadIdx.x & 31;
    if (gwarp >= N_RAYS) return;

    const float offx = -51.2f, offy = -51.2f, offz = -3.2f;
    const float inv_vox = 5.0f;  // 1/0.2

    int ti = tindex[gwarp];

    float ox = (origin[ti * 3 + 0] - offx) * inv_vox;
    float oy = (origin[ti * 3 + 1] - offy) * inv_vox;
    float oz = (origin[ti * 3 + 2] - offz) * inv_vox;

    float px = (points[gwarp * 3 + 0] - offx) * inv_vox;
    float py = (points[gwarp * 3 + 1] - offy) * inv_vox;
    float pz = (points[gwarp * 3 + 2] - offz) * inv_vox;

    float dx = px - ox, dy = py - oy, dz = pz - oz;
    float gt = sqrtf(dx * dx + dy * dy + dz * dz);
    float rinv = 1.0f / fmaxf(gt, 1e-6f);
    float ux = dx * rinv, uy = dy * rinv, uz = dz * rinv;

    const float* base = grid + (size_t)ti * (ZZ * YY * XX);

    float S = 0.0f;     // cumulative tau from prior chunks
    float pred = 0.0f;  // per-lane partial of sum(w * t)

    #pragma unroll 1
    for (int c = 0; c < N_STEPS / 32; ++c) {
        float t = (float)(c * 32 + lane) + 0.5f;
        float fx = ox + ux * t;
        float fy = oy + uy * t;
        float fz = oz + uz * t;
        int ix = (int)floorf(fx);
        int iy = (int)floorf(fy);
        int iz = (int)floorf(fz);
        bool inb = (ix >= 0) & (ix < XX) & (iy >= 0) & (iy < YY) &
                   (iz >= 0) & (iz < ZZ);
        float tau = 0.0f;
        if (inb) {
            float sig = base[((size_t)iz * YY + iy) * XX + ix];
            tau = fmaxf(sig, 0.0f);
        }

        // Warp inclusive scan of tau
        float scan = tau;
        #pragma unroll
        for (int o = 1; o < 32; o <<= 1) {
            float v = __shfl_up_sync(FULL, scan, o);
            if (lane >= o) scan += v;
        }
        float excl = scan - tau;

        float trans = expf(-(S + excl));
        pred += trans * (1.0f - expf(-tau)) * t;

        S += __shfl_sync(FULL, scan, 31);
    }

    // Warp reduction of pred
    #pragma unroll
    for (int o = 16; o > 0; o >>= 1)
        pred += __shfl_xor_sync(FULL, pred, o);

    if (lane == 0) {
        g_pred[gwarp] = pred * VOXEL;
        g_gt[gwarp]   = gt * VOXEL;
    }
}

__global__ void loss_reduce_kernel(float* __restrict__ out)
{
    __shared__ float sh1[256], sh2[256], sh3[256];
    float l1 = 0.0f, l2 = 0.0f, ar = 0.0f;
    for (int i = threadIdx.x; i < N_RAYS; i += blockDim.x) {
        float gt = g_gt[i];
        float pr = g_pred[i];
        // valid = gt >= 0 (always true for a norm); count = N_RAYS
        float d  = gt - pr;
        float ad = fabsf(d);
        l1 += ad;
        l2 += 0.5f * d * d;
        ar += ad / fmaxf(gt, 1e-6f);
    }
    int tid = threadIdx.x;
    sh1[tid] = l1; sh2[tid] = l2; sh3[tid] = ar;
    __syncthreads();
    for (int s = 128; s > 0; s >>= 1) {
        if (tid < s) {
            sh1[tid] += sh1[tid + s];
            sh2[tid] += sh2[tid + s];
            sh3[tid] += sh3[tid + s];
        }
        __syncthreads();
    }
    if (tid == 0) {
        float inv_count = 1.0f / (float)N_RAYS;
        out[0] = sh1[0] * inv_count;
        out[1] = sh2[0] * inv_count;
        out[2] = sh3[0] * inv_count;
    }
}

extern "C" void kernel_launch(void* const* d_in, const int* in_sizes, int n_in,
                              void* d_out, int out_size)
{
    const float* grid    = (const float*)d_in[0];  // [1,5,32,512,512]
    const float* origin  = (const float*)d_in[1];  // [1,5,3]
    const float* points  = (const float*)d_in[2];  // [1,10000,3]
    const int*   tindex  = (const int*)d_in[3];    // [1,10000]
    float* out = (float*)d_out;

    // 10000 rays, one warp each: 320000 threads, 256 threads/block
    int threads = 256;
    int blocks = (N_RAYS * 32 + threads - 1) / threads;
    ray_march_kernel<<<blocks, threads>>>(grid, origin, points, tindex);
    loss_reduce_kernel<<<1, 256>>>(out);
}

// round 2
// speedup vs baseline: 2.7569x; 2.7569x over previous
#include <cuda_runtime.h>
#include <math.h>

#define TT 5
#define ZZ 32
#define YY 512
#define XX 512
#define N_RAYS 10000
#define N_STEPS 768
#define VOXEL 0.2f
#define N_CHUNKS (N_STEPS / 32)

__global__ void zero_out_kernel(float* __restrict__ out)
{
    out[0] = 0.0f;
    out[1] = 0.0f;
    out[2] = 0.0f;
}

__device__ __forceinline__ float fetch_tau(const float* __restrict__ base,
                                           float ox, float oy, float oz,
                                           float ux, float uy, float uz,
                                           int c, int lane)
{
    float t = (float)(c * 32 + lane) + 0.5f;
    float fx = ox + ux * t;
    float fy = oy + uy * t;
    float fz = oz + uz * t;
    int ix = (int)floorf(fx);
    int iy = (int)floorf(fy);
    int iz = (int)floorf(fz);
    bool inb = (ix >= 0) & (ix < XX) & (iy >= 0) & (iy < YY) &
               (iz >= 0) & (iz < ZZ);
    float tau = 0.0f;
    if (inb) {
        float sig = __ldg(base + ((size_t)iz * YY + iy) * XX + ix);
        tau = fmaxf(sig, 0.0f);
    }
    return tau;
}

__global__ void ray_march_loss_kernel(const float* __restrict__ grid,
                                      const float* __restrict__ origin,   // [T,3]
                                      const float* __restrict__ points,   // [N_RAYS,3]
                                      const int*   __restrict__ tindex,   // [N_RAYS]
                                      float* __restrict__ out)            // [3]
{
    const unsigned FULL = 0xffffffffu;
    int gwarp = (blockIdx.x * blockDim.x + threadIdx.x) >> 5;
    int lane  = threadIdx.x & 31;
    int wid   = threadIdx.x >> 5;   // warp in block (0..7)

    __shared__ float s1[8], s2[8], s3[8];

    float l1 = 0.0f, l2 = 0.0f, l3 = 0.0f;

    if (gwarp < N_RAYS) {
        const float offx = -51.2f, offy = -51.2f, offz = -3.2f;
        const float inv_vox = 5.0f;  // 1/0.2

        int ti = tindex[gwarp];

        float ox = (origin[ti * 3 + 0] - offx) * inv_vox;
        float oy = (origin[ti * 3 + 1] - offy) * inv_vox;
        float oz = (origin[ti * 3 + 2] - offz) * inv_vox;

        float px = (points[gwarp * 3 + 0] - offx) * inv_vox;
        float py = (points[gwarp * 3 + 1] - offy) * inv_vox;
        float pz = (points[gwarp * 3 + 2] - offz) * inv_vox;

        float dx = px - ox, dy = py - oy, dz = pz - oz;
        float gt = sqrtf(dx * dx + dy * dy + dz * dz);
        float rinv = 1.0f / fmaxf(gt, 1e-6f);
        float ux = dx * rinv, uy = dy * rinv, uz = dz * rinv;

        // ---- Slab clipping: find t-range where the sample point is inside
        //      [0,X) x [0,Y) x [0,Z). Widened by 1 step; per-lane inb guard
        //      below keeps correctness regardless.
        float tmin = 0.0f, tmax = (float)N_STEPS;
        bool empty = false;
        {
            float o[3] = {ox, oy, oz};
            float u[3] = {ux, uy, uz};
            float dim[3] = {(float)XX, (float)YY, (float)ZZ};
            #pragma unroll
            for (int a = 0; a < 3; ++a) {
                if (fabsf(u[a]) > 1e-8f) {
                    float inv = 1.0f / u[a];
                    float t0 = (0.0f  - o[a]) * inv;
                    float t1 = (dim[a] - o[a]) * inv;
                    float tn = fminf(t0, t1), tf = fmaxf(t0, t1);
                    tmin = fmaxf(tmin, tn);
                    tmax = fminf(tmax, tf);
                } else if (o[a] < 0.0f || o[a] >= dim[a]) {
                    empty = true;
                }
            }
        }

        float pred = 0.0f;

        if (!empty && tmax > tmin) {
            int k_lo = (int)floorf(tmin - 0.5f) - 1;
            int k_hi = (int)ceilf (tmax - 0.5f) + 1;
            k_lo = max(0, k_lo);
            k_hi = min(N_STEPS - 1, k_hi);
            int c0 = k_lo >> 5;
            int c1 = k_hi >> 5;

            const float* base = grid + (size_t)ti * (ZZ * YY * XX);

            float S = 0.0f;
            float tau_next = fetch_tau(base, ox, oy, oz, ux, uy, uz, c0, lane);

            #pragma unroll 1
            for (int c = c0; c <= c1; ++c) {
                float tau = tau_next;
                if (c < c1)
                    tau_next = fetch_tau(base, ox, oy, oz, ux, uy, uz, c + 1, lane);

                // Warp inclusive scan of tau
                float scan = tau;
                #pragma unroll
                for (int o = 1; o < 32; o <<= 1) {
                    float v = __shfl_up_sync(FULL, scan, o);
                    if (lane >= o) scan += v;
                }
                float excl = scan - tau;

                float t = (float)(c * 32 + lane) + 0.5f;
                float trans = __expf(-(S + excl));
                pred += trans * (1.0f - __expf(-tau)) * t;

                S += __shfl_sync(FULL, scan, 31);
                if (S > 25.0f) break;   // trans < 1.4e-11: tail negligible
            }

            // Warp reduction of pred
            #pragma unroll
            for (int o = 16; o > 0; o >>= 1)
                pred += __shfl_xor_sync(FULL, pred, o);
        }

        if (lane == 0) {
            float p = pred * VOXEL;
            float g = gt * VOXEL;
            float d = g - p;
            float ad = fabsf(d);
            l1 = ad;
            l2 = 0.5f * d * d;
            l3 = ad / fmaxf(g, 1e-6f);
        }
    }

    // Block reduction: lane0 of each warp holds this warp's contribution
    if (lane == 0) {
        s1[wid] = l1; s2[wid] = l2; s3[wid] = l3;
    }
    __syncthreads();
    if (wid == 0 && lane == 0) {
        float a = 0.0f, b = 0.0f, cc = 0.0f;
        #pragma unroll
        for (int i = 0; i < 8; ++i) { a += s1[i]; b += s2[i]; cc += s3[i]; }
        const float inv_count = 1.0f / (float)N_RAYS;
        atomicAdd(&out[0], a  * inv_count);
        atomicAdd(&out[1], b  * inv_count);
        atomicAdd(&out[2], cc * inv_count);
    }
}

extern "C" void kernel_launch(void* const* d_in, const int* in_sizes, int n_in,
                              void* d_out, int out_size)
{
    const float* grid    = (const float*)d_in[0];  // [1,5,32,512,512]
    const float* origin  = (const float*)d_in[1];  // [1,5,3]
    const float* points  = (const float*)d_in[2];  // [1,10000,3]
    const int*   tindex  = (const int*)d_in[3];    // [1,10000]
    float* out = (float*)d_out;

    zero_out_kernel<<<1, 1>>>(out);

    int threads = 256;  // 8 warps = 8 rays per block
    int blocks = (N_RAYS * 32 + threads - 1) / threads;
    ray_march_loss_kernel<<<blocks, threads>>>(grid, origin, points, tindex, out);
}